// round 10
// baseline (speedup 1.0000x reference)
#include <cuda_runtime.h>
#include <cuda_bf16.h>
#include <cstdint>

// Problem constants
#define Bc 32
#define Tc 256
#define Hc 512
#define Vc 32000
#define NBLK 128   // persistent recurrence grid (1 block/SM => co-resident)

// K3 split-GEMM constants
#define GKB 1536            // split-K total (3 x 512)
#define KCH 32              // bf16 per K chunk
#define NCHUNK (GKB / KCH)  // 48
#define SROW 80             // SMEM row stride bytes -> ldmatrix conflict-free
#define NSTG 3
#define STG_BYTES ((128 + 256) * SROW)   // A(128 rows)+B(256 rows) per stage = 30720
#define TC_SMEM (NSTG * STG_BYTES)       // 92160

// ---------------------------------------------------------------------------
// Scratch (device globals: allocation-free per harness rules)
// ---------------------------------------------------------------------------
__device__ float g_gi0[Tc * Bc * 3 * Hc];
__device__ float g_outs[Bc * Tc * Hc];
__device__ float g_h[Bc * Hc];
__device__ float g_h1[Bc * Hc];
__device__ unsigned g_barcnt;
__device__ unsigned g_bargen;
__device__ __nv_bfloat16 g_abf[(size_t)Bc * Tc * GKB];   // [8192][1536] = [hi|hi|lo]
__device__ __nv_bfloat16 g_bbf[(size_t)Vc * GKB];        // [32000][1536] = [hi|lo|hi]

// ---------------------------------------------------------------------------
// Baseline-ISA PTX helpers (sm_80+ only; NO 'a'-suffix instructions)
// ---------------------------------------------------------------------------
__device__ __forceinline__ uint32_t smem_u32(const void* p) {
    uint32_t a;
    asm("{ .reg .u64 t; cvta.to.shared.u64 t, %1; cvt.u32.u64 %0, t; }"
        : "=r"(a) : "l"(p));
    return a;
}

#define CP16(dst, src) \
    asm volatile("cp.async.cg.shared.global [%0], [%1], 16;" \
                 :: "r"(dst), "l"(src))
#define CP_COMMIT() asm volatile("cp.async.commit_group;" ::: "memory")
#define CP_WAIT(n)  asm volatile("cp.async.wait_group %0;" :: "n"(n) : "memory")

#define LDSM4(r0, r1, r2, r3, addr) \
    asm volatile("ldmatrix.sync.aligned.m8n8.x4.shared.b16 {%0,%1,%2,%3}, [%4];" \
                 : "=r"(r0), "=r"(r1), "=r"(r2), "=r"(r3) : "r"(addr))

#define MMA16816(d, a, b) \
    asm volatile("mma.sync.aligned.m16n8k16.row.col.f32.bf16.bf16.f32 " \
                 "{%0,%1,%2,%3}, {%4,%5,%6,%7}, {%8,%9}, {%0,%1,%2,%3};" \
                 : "+f"((d)[0]), "+f"((d)[1]), "+f"((d)[2]), "+f"((d)[3]) \
                 : "r"((a)[0]), "r"((a)[1]), "r"((a)[2]), "r"((a)[3]), \
                   "r"((b)[0]), "r"((b)[1]))

// ---------------------------------------------------------------------------
// Grid barrier for the recurrence kernel
// ---------------------------------------------------------------------------
__device__ __forceinline__ void gridbar() {
    __syncthreads();
    if (threadIdx.x == 0) {
        __threadfence();
        unsigned gen = *(volatile unsigned*)&g_bargen;
        if (atomicAdd(&g_barcnt, 1u) == NBLK - 1) {
            atomicExch(&g_barcnt, 0u);
            __threadfence();
            atomicAdd(&g_bargen, 1u);
        } else {
            while (*(volatile unsigned*)&g_bargen == gen) __nanosleep(64);
        }
        __threadfence();
    }
    __syncthreads();
}

__device__ __forceinline__ float sigm(float v) { return 1.f / (1.f + __expf(-v)); }

// ---------------------------------------------------------------------------
// K1: fp32 GEMM with fused embedding gather (unchanged)
// ---------------------------------------------------------------------------
template <int MODE>
__global__ void __launch_bounds__(256, 2)
gemm_tn(const float* __restrict__ A, const float* __restrict__ W,
        const float* __restrict__ bias, float* __restrict__ C,
        const int* __restrict__ xidx, int N)
{
    __shared__ float As[16 * 128];
    __shared__ float Bs[16 * 128];

    const int tid  = threadIdx.x;
    const int m0   = blockIdx.y * 128;
    const int n0   = blockIdx.x * 128;
    const int lrow = tid >> 2;
    const int lk   = (tid & 3) * 4;
    const int ty   = tid >> 4;
    const int tx   = tid & 15;

    const float *ap0, *ap1;
    {
        int ma0 = m0 + lrow, ma1 = ma0 + 64;
        if (MODE == 1) {
            int r0 = xidx[(ma0 & 31) * Tc + (ma0 >> 5)];
            int r1 = xidx[(ma1 & 31) * Tc + (ma1 >> 5)];
            ap0 = A + (size_t)r0 * Hc;
            ap1 = A + (size_t)r1 * Hc;
        } else {
            ap0 = A + (size_t)ma0 * Hc;
            ap1 = A + (size_t)ma1 * Hc;
        }
    }
    const float* bp0 = W + (size_t)(n0 + lrow) * Hc;
    const float* bp1 = bp0 + (size_t)64 * Hc;

    float acc[8][8];
#pragma unroll
    for (int i = 0; i < 8; i++)
#pragma unroll
        for (int j = 0; j < 8; j++) acc[i][j] = 0.f;

    for (int kt = 0; kt < Hc; kt += 16) {
        float4 a0 = *(const float4*)(ap0 + kt + lk);
        float4 a1 = *(const float4*)(ap1 + kt + lk);
        float4 b0 = *(const float4*)(bp0 + kt + lk);
        float4 b1 = *(const float4*)(bp1 + kt + lk);
        __syncthreads();
        As[(lk + 0) * 128 + lrow]      = a0.x;
        As[(lk + 1) * 128 + lrow]      = a0.y;
        As[(lk + 2) * 128 + lrow]      = a0.z;
        As[(lk + 3) * 128 + lrow]      = a0.w;
        As[(lk + 0) * 128 + lrow + 64] = a1.x;
        As[(lk + 1) * 128 + lrow + 64] = a1.y;
        As[(lk + 2) * 128 + lrow + 64] = a1.z;
        As[(lk + 3) * 128 + lrow + 64] = a1.w;
        Bs[(lk + 0) * 128 + lrow]      = b0.x;
        Bs[(lk + 1) * 128 + lrow]      = b0.y;
        Bs[(lk + 2) * 128 + lrow]      = b0.z;
        Bs[(lk + 3) * 128 + lrow]      = b0.w;
        Bs[(lk + 0) * 128 + lrow + 64] = b1.x;
        Bs[(lk + 1) * 128 + lrow + 64] = b1.y;
        Bs[(lk + 2) * 128 + lrow + 64] = b1.z;
        Bs[(lk + 3) * 128 + lrow + 64] = b1.w;
        __syncthreads();
#pragma unroll
        for (int kk = 0; kk < 16; kk++) {
            float4 av0 = *(const float4*)&As[kk * 128 + ty * 8];
            float4 av1 = *(const float4*)&As[kk * 128 + ty * 8 + 4];
            float4 bv0 = *(const float4*)&Bs[kk * 128 + tx * 8];
            float4 bv1 = *(const float4*)&Bs[kk * 128 + tx * 8 + 4];
            float a[8] = {av0.x, av0.y, av0.z, av0.w, av1.x, av1.y, av1.z, av1.w};
            float b[8] = {bv0.x, bv0.y, bv0.z, bv0.w, bv1.x, bv1.y, bv1.z, bv1.w};
#pragma unroll
            for (int i = 0; i < 8; i++)
#pragma unroll
                for (int j = 0; j < 8; j++) acc[i][j] += a[i] * b[j];
        }
    }

    float bs[8];
#pragma unroll
    for (int j = 0; j < 8; j++) bs[j] = bias[n0 + tx * 8 + j];
#pragma unroll
    for (int i = 0; i < 8; i++) {
        size_t base = (size_t)(m0 + ty * 8 + i) * (size_t)N + n0 + tx * 8;
        float4 o0 = make_float4(acc[i][0] + bs[0], acc[i][1] + bs[1],
                                acc[i][2] + bs[2], acc[i][3] + bs[3]);
        float4 o1 = make_float4(acc[i][4] + bs[4], acc[i][5] + bs[5],
                                acc[i][6] + bs[6], acc[i][7] + bs[7]);
        *(float4*)&C[base]     = o0;
        *(float4*)&C[base + 4] = o1;
    }
}

// ---------------------------------------------------------------------------
// K2: persistent GRU recurrence (unchanged — passing since R5)
// ---------------------------------------------------------------------------
#define REC_SMEM_FLOATS (12 * 512 + 24 * 512 + 512 * 33 + 768)

__global__ void __launch_bounds__(256, 1)
gru_rec(const float* __restrict__ Wih, const float* __restrict__ Whh,
        const float* __restrict__ bih, const float* __restrict__ bhh)
{
    extern __shared__ float sm[];
    float* ws1  = sm;
    float* ws2  = sm + 12 * 512;
    float* hs   = sm + 36 * 512;
    float* psum = hs + 512 * 33;

    const int tid = threadIdx.x;
    const int bk  = blockIdx.x;
    const int j0  = bk * 4;

    const float* Whh0 = Whh;
    const float* Wih1 = Wih + 1536 * 512;
    const float* Whh1 = Whh + 1536 * 512;

    for (int idx = tid; idx < 12 * 512; idx += 256) {
        int rl = idx >> 9, k = idx & 511;
        int jj = rl / 3, g = rl % 3;
        ws1[idx] = Whh0[(size_t)(g * Hc + j0 + jj) * Hc + k];
    }
    for (int idx = tid; idx < 24 * 512; idx += 256) {
        int rl = idx >> 9, k = idx & 511;
        int jj = rl / 6, g = rl % 6;
        const float* src = (g < 3) ? Wih1 : Whh1;
        int gg = (g < 3) ? g : g - 3;
        ws2[idx] = src[(size_t)(gg * Hc + j0 + jj) * Hc + k];
    }
    {
        int i = bk * 256 + tid;
        if (i < Bc * Hc) g_h[i] = 0.f;
    }

    const int out = tid & 127;
    const int b   = out & 31;
    const int jj  = out >> 5;
    const int kh  = tid >> 7;
    const int j   = j0 + jj;

    const float bhh0r = bhh[j],          bhh0z = bhh[Hc + j],          bhh0n = bhh[2 * Hc + j];
    const float bih1r = bih[3 * Hc + j], bih1z = bih[4 * Hc + j],      bih1n = bih[5 * Hc + j];
    const float bhh1r = bhh[3 * Hc + j], bhh1z = bhh[4 * Hc + j],      bhh1n = bhh[5 * Hc + j];

    gridbar();

    for (int t = 0; t < Tc; t++) {
        for (int i = tid; i < Bc * Hc; i += 256) {
            int bb = i >> 9, k = i & 511;
            hs[k * 33 + bb] = __ldcg(&g_h[i]);
        }
        __syncthreads();
        {
            const float* wr = ws1 + (jj * 3) * Hc + kh * 256;
            const float* wz = wr + Hc;
            const float* wn = wz + Hc;
            const float* hp = hs + (kh * 256) * 33 + b;
            float sr = 0.f, sz = 0.f, sn = 0.f;
#pragma unroll 8
            for (int k = 0; k < 256; k += 4) {
                float4 vr = *(const float4*)(wr + k);
                float4 vz = *(const float4*)(wz + k);
                float4 vn = *(const float4*)(wn + k);
                float h0 = hp[(k + 0) * 33], h1v = hp[(k + 1) * 33];
                float h2 = hp[(k + 2) * 33], h3v = hp[(k + 3) * 33];
                sr += vr.x * h0 + vr.y * h1v + vr.z * h2 + vr.w * h3v;
                sz += vz.x * h0 + vz.y * h1v + vz.z * h2 + vz.w * h3v;
                sn += vn.x * h0 + vn.y * h1v + vn.z * h2 + vn.w * h3v;
            }
            if (kh) { psum[out * 3 + 0] = sr; psum[out * 3 + 1] = sz; psum[out * 3 + 2] = sn; }
            __syncthreads();
            if (!kh) {
                sr += psum[out * 3 + 0]; sz += psum[out * 3 + 1]; sn += psum[out * 3 + 2];
                const float* gi = g_gi0 + (size_t)(t * Bc + b) * 1536;
                float r = sigm(gi[j] + sr + bhh0r);
                float z = sigm(gi[Hc + j] + sz + bhh0z);
                float n = tanhf(gi[2 * Hc + j] + r * (sn + bhh0n));
                float hprev = hs[j * 33 + b];
                g_h1[b * Hc + j] = (1.f - z) * n + z * hprev;
            }
        }
        gridbar();

        for (int i = tid; i < Bc * Hc; i += 256) {
            int bb = i >> 9, k = i & 511;
            hs[k * 33 + bb] = __ldcg(&g_h1[i]);
        }
        __syncthreads();
        {
            const float* w0 = ws2 + (jj * 6) * Hc + kh * 256;
            const float* hp = hs + (kh * 256) * 33 + b;
            float s0 = 0.f, s1 = 0.f, s2 = 0.f, s3 = 0.f, s4 = 0.f, s5 = 0.f;
#pragma unroll 4
            for (int k = 0; k < 256; k += 4) {
                float4 v0 = *(const float4*)(w0 + k);
                float4 v1 = *(const float4*)(w0 + Hc + k);
                float4 v2 = *(const float4*)(w0 + 2 * Hc + k);
                float4 v3 = *(const float4*)(w0 + 3 * Hc + k);
                float4 v4 = *(const float4*)(w0 + 4 * Hc + k);
                float4 v5 = *(const float4*)(w0 + 5 * Hc + k);
                float h0 = hp[(k + 0) * 33], h1v = hp[(k + 1) * 33];
                float h2 = hp[(k + 2) * 33], h3v = hp[(k + 3) * 33];
                s0 += v0.x * h0 + v0.y * h1v + v0.z * h2 + v0.w * h3v;
                s1 += v1.x * h0 + v1.y * h1v + v1.z * h2 + v1.w * h3v;
                s2 += v2.x * h0 + v2.y * h1v + v2.z * h2 + v2.w * h3v;
                s3 += v3.x * h0 + v3.y * h1v + v3.z * h2 + v3.w * h3v;
                s4 += v4.x * h0 + v4.y * h1v + v4.z * h2 + v4.w * h3v;
                s5 += v5.x * h0 + v5.y * h1v + v5.z * h2 + v5.w * h3v;
            }
            if (kh) {
                psum[out * 6 + 0] = s0; psum[out * 6 + 1] = s1; psum[out * 6 + 2] = s2;
                psum[out * 6 + 3] = s3; psum[out * 6 + 4] = s4; psum[out * 6 + 5] = s5;
            }
            __syncthreads();
            if (!kh) {
                s0 += psum[out * 6 + 0]; s1 += psum[out * 6 + 1]; s2 += psum[out * 6 + 2];
                s3 += psum[out * 6 + 3]; s4 += psum[out * 6 + 4]; s5 += psum[out * 6 + 5];
                float r = sigm((s0 + bih1r) + (s3 + bhh1r));
                float z = sigm((s1 + bih1z) + (s4 + bhh1z));
                float n = tanhf((s2 + bih1n) + r * (s5 + bhh1n));
                float h1v = hs[j * 33 + b];
                float h2 = (1.f - z) * n + z * h1v;
                g_h[b * Hc + j] = h2;
                g_outs[(size_t)(b * Tc + t) * Hc + j] = h2;
            }
        }
        gridbar();
    }
}

// ---------------------------------------------------------------------------
// Split-bf16 conversion kernels (unchanged)
// ---------------------------------------------------------------------------
__global__ void conv_a() {
    int i = blockIdx.x * 256 + threadIdx.x;
    if (i >= Bc * Tc * Hc) return;
    int m = i >> 9, k = i & 511;
    float x = g_outs[i];
    __nv_bfloat16 hi = __float2bfloat16(x);
    __nv_bfloat16 lo = __float2bfloat16(x - __bfloat162float(hi));
    size_t base = (size_t)m * GKB + k;
    g_abf[base]        = hi;
    g_abf[base + 512]  = hi;
    g_abf[base + 1024] = lo;
}

__global__ void conv_b(const float* __restrict__ Wout) {
    int i = blockIdx.x * 256 + threadIdx.x;
    if (i >= Vc * Hc) return;
    int n = i >> 9, k = i & 511;
    float x = Wout[i];
    __nv_bfloat16 hi = __float2bfloat16(x);
    __nv_bfloat16 lo = __float2bfloat16(x - __bfloat162float(hi));
    size_t base = (size_t)n * GKB + k;
    g_bbf[base]        = hi;
    g_bbf[base + 512]  = lo;
    g_bbf[base + 1024] = hi;
}

// ---------------------------------------------------------------------------
// K3: HMMA GEMM, CTA tile 128x256, warp tile 64x64 (2Mx4N warps),
// 3-stage cp.async pipeline, ONE __syncthreads per K32 chunk.
// Stage layout: [A 128 rows | B 256 rows] x SROW bytes.
// ---------------------------------------------------------------------------
__global__ void __launch_bounds__(256, 1)
gemm_hmma(const float* __restrict__ bout, float* __restrict__ C)
{
    extern __shared__ __align__(16) char smc[];
    const uint32_t sb = smem_u32(smc);
    const int tid  = threadIdx.x;
    const int lane = tid & 31;
    const int wid  = tid >> 5;
    const int wm   = wid & 1;            // 2 warps in M
    const int wn   = wid >> 1;           // 4 warps in N
    const int m0   = blockIdx.x * 128;   // m fastest: A' (25MB) L2-resident
    const int n0   = blockIdx.y * 256;

    const __nv_bfloat16* Ag = g_abf + (size_t)m0 * GKB;
    const __nv_bfloat16* Bg = g_bbf + (size_t)n0 * GKB;

    float acc[4][8][4];
#pragma unroll
    for (int mb = 0; mb < 4; mb++)
#pragma unroll
        for (int nb = 0; nb < 8; nb++)
#pragma unroll
            for (int q = 0; q < 4; q++) acc[mb][nb][q] = 0.f;

    // chunk loader: A 128 rows + B 256 rows, 4 x 16B segs per row
    auto load_chunk = [&](int c) {
        const uint32_t stg = sb + (uint32_t)(c % NSTG) * STG_BYTES;
        const int kc = c * KCH;
        // A: 512 segs = 2 rounds
#pragma unroll
        for (int r = 0; r < 2; r++) {
            int seg = tid + r * 256;
            int row = seg >> 2, i = seg & 3;
            CP16(stg + (uint32_t)(row * SROW + i * 16),
                 Ag + (size_t)row * GKB + kc + i * 8);
        }
        // B: 1024 segs = 4 rounds
        const uint32_t stgB = stg + 128 * SROW;
#pragma unroll
        for (int r = 0; r < 4; r++) {
            int seg = tid + r * 256;
            int row = seg >> 2, i = seg & 3;
            CP16(stgB + (uint32_t)(row * SROW + i * 16),
                 Bg + (size_t)row * GKB + kc + i * 8);
        }
    };

    load_chunk(0); CP_COMMIT();
    load_chunk(1); CP_COMMIT();

    for (int c = 0; c < NCHUNK; c++) {
        CP_WAIT(1);                 // chunk c landed (c+1 may be in flight)
        __syncthreads();            // all warps done reading stage (c-1)%3

        if (c + 2 < NCHUNK) load_chunk(c + 2);   // into stage (c-1)%3, overlaps MMAs
        CP_COMMIT();                              // uniform group accounting

        const uint32_t aB = sb + (uint32_t)(c % NSTG) * STG_BYTES;
        const uint32_t bB = aB + 128 * SROW;

#pragma unroll
        for (int kk = 0; kk < 2; kk++) {      // two k16 steps per 32-chunk
            uint32_t a[4][4];
            {
                uint32_t addr = aB + (uint32_t)((wm * 64 + (lane & 15)) * SROW
                                  + (kk * 16 + ((lane >> 4) << 3)) * 2);
#pragma unroll
                for (int mb = 0; mb < 4; mb++)
                    LDSM4(a[mb][0], a[mb][1], a[mb][2], a[mb][3],
                          addr + (uint32_t)(mb * 16 * SROW));
            }
            uint32_t b[8][2];
            {
                const int q = lane >> 3, rr = lane & 7;
                const int nbase = wn * 64 + ((q & 2) << 2) + rr;   // +8 for q>=2
                const int kcol  = kk * 16 + ((q & 1) << 3);
#pragma unroll
                for (int p = 0; p < 4; p++) {
                    uint32_t addr = bB + (uint32_t)((nbase + p * 16) * SROW + kcol * 2);
                    LDSM4(b[2 * p][0], b[2 * p][1], b[2 * p + 1][0], b[2 * p + 1][1], addr);
                }
            }
#pragma unroll
            for (int mb = 0; mb < 4; mb++)
#pragma unroll
                for (int nb = 0; nb < 8; nb++)
                    MMA16816(acc[mb][nb], a[mb], b[nb]);
        }
    }

    // epilogue: d-frag (m16n8): rows lane>>2 (+8), cols (lane&3)*2
#pragma unroll
    for (int mb = 0; mb < 4; mb++) {
        const int row = m0 + wm * 64 + mb * 16 + (lane >> 2);
#pragma unroll
        for (int nb = 0; nb < 8; nb++) {
            const int col = n0 + wn * 64 + nb * 8 + (lane & 3) * 2;
            const float b0 = __ldg(&bout[col]);
            const float b1 = __ldg(&bout[col + 1]);
            float2 o0 = make_float2(acc[mb][nb][0] + b0, acc[mb][nb][1] + b1);
            float2 o1 = make_float2(acc[mb][nb][2] + b0, acc[mb][nb][3] + b1);
            *(float2*)&C[(size_t)row * Vc + col]       = o0;
            *(float2*)&C[(size_t)(row + 8) * Vc + col] = o1;
        }
    }
}

// ---------------------------------------------------------------------------
// Launch
// ---------------------------------------------------------------------------
extern "C" void kernel_launch(void* const* d_in, const int* in_sizes, int n_in,
                              void* d_out, int out_size)
{
    const int*   x    = (const int*)d_in[0];
    const float* emb  = (const float*)d_in[1];
    const float* Wih  = (const float*)d_in[2];
    const float* Whh  = (const float*)d_in[3];
    const float* bih  = (const float*)d_in[4];
    const float* bhh  = (const float*)d_in[5];
    const float* Wout = (const float*)d_in[6];
    const float* bout = (const float*)d_in[7];
    float* out = (float*)d_out;

    void* p;
    cudaGetSymbolAddress(&p, g_gi0);  float* gi0 = (float*)p;

    // K1: gi0[t*32+b][0:1536] = emb[x[b][t]] @ Wih0^T + bih0
    dim3 g1(1536 / 128, (Bc * Tc) / 128);
    gemm_tn<1><<<g1, 256>>>(emb, Wih, bih, gi0, x, 1536);

    // B' split conversion (independent of recurrence)
    conv_b<<<(Vc * Hc + 255) / 256, 256>>>(Wout);

    // K2: persistent recurrence
    size_t smem = REC_SMEM_FLOATS * sizeof(float);
    cudaFuncSetAttribute(gru_rec, cudaFuncAttributeMaxDynamicSharedMemorySize, (int)smem);
    gru_rec<<<NBLK, 256, smem>>>(Wih, Whh, bih, bhh);

    // A' split conversion (needs g_outs)
    conv_a<<<(Bc * Tc * Hc + 255) / 256, 256>>>();

    // K3: logits = A' @ B'^T + bout via mma.sync bf16 (split, K'=1536)
    cudaFuncSetAttribute(gemm_hmma, cudaFuncAttributeMaxDynamicSharedMemorySize, TC_SMEM);
    dim3 g3((Bc * Tc) / 128, Vc / 256);   // (64, 125), m fastest
    gemm_hmma<<<g3, 256, TC_SMEM>>>(bout, out);
}

// round 13
// speedup vs baseline: 1.1581x; 1.1581x over previous
#include <cuda_runtime.h>
#include <cuda_fp16.h>
#include <cstdint>

// Problem constants
#define Bc 32
#define Tc 256
#define Hc 512
#define Vc 32000
#define NBLK 128   // persistent recurrence grid (1 block/SM => co-resident)

// K3 split-GEMM constants (fp16 2-term: A'=[hi|lo], B'=[hi|hi])
#define GKB 1024            // split-K total (2 x 512)
#define KCH 32              // fp16 per K chunk (64B row)
#define NCHUNK (GKB / KCH)  // 32
#define SROW 80             // SMEM row stride bytes -> ldmatrix conflict-free
#define NSTG 4
#define STG_BYTES ((128 + 128) * SROW)   // A(128)+B(128) rows = 20480
#define TC_SMEM (NSTG * STG_BYTES)       // 81920 (2 CTAs/SM: 163840 < 228KB)

// ---------------------------------------------------------------------------
// Scratch (device globals: allocation-free per harness rules)
// ---------------------------------------------------------------------------
__device__ float g_gi0[Tc * Bc * 3 * Hc];
__device__ float g_outs[Bc * Tc * Hc];
__device__ float g_h[Bc * Hc];
__device__ float g_h1[Bc * Hc];
__device__ unsigned g_barcnt;
__device__ unsigned g_bargen;
__device__ __half g_abf[(size_t)Bc * Tc * GKB];   // [8192][1024] = [hi|lo]
__device__ __half g_bbf[(size_t)Vc * GKB];        // [32000][1024] = [hi|hi]

// ---------------------------------------------------------------------------
// Baseline-ISA PTX helpers (sm_80+ only; NO 'a'-suffix instructions)
// ---------------------------------------------------------------------------
__device__ __forceinline__ uint32_t smem_u32(const void* p) {
    uint32_t a;
    asm("{ .reg .u64 t; cvta.to.shared.u64 t, %1; cvt.u32.u64 %0, t; }"
        : "=r"(a) : "l"(p));
    return a;
}

#define CP16(dst, src) \
    asm volatile("cp.async.cg.shared.global [%0], [%1], 16;" \
                 :: "r"(dst), "l"(src))
#define CP_COMMIT() asm volatile("cp.async.commit_group;" ::: "memory")
#define CP_WAIT(n)  asm volatile("cp.async.wait_group %0;" :: "n"(n) : "memory")

#define LDSM4(r0, r1, r2, r3, addr) \
    asm volatile("ldmatrix.sync.aligned.m8n8.x4.shared.b16 {%0,%1,%2,%3}, [%4];" \
                 : "=r"(r0), "=r"(r1), "=r"(r2), "=r"(r3) : "r"(addr))

#define MMA16816(d, a, b) \
    asm volatile("mma.sync.aligned.m16n8k16.row.col.f32.f16.f16.f32 " \
                 "{%0,%1,%2,%3}, {%4,%5,%6,%7}, {%8,%9}, {%0,%1,%2,%3};" \
                 : "+f"((d)[0]), "+f"((d)[1]), "+f"((d)[2]), "+f"((d)[3]) \
                 : "r"((a)[0]), "r"((a)[1]), "r"((a)[2]), "r"((a)[3]), \
                   "r"((b)[0]), "r"((b)[1]))

// ---------------------------------------------------------------------------
// Grid barrier for the recurrence kernel
// ---------------------------------------------------------------------------
__device__ __forceinline__ void gridbar() {
    __syncthreads();
    if (threadIdx.x == 0) {
        __threadfence();
        unsigned gen = *(volatile unsigned*)&g_bargen;
        if (atomicAdd(&g_barcnt, 1u) == NBLK - 1) {
            atomicExch(&g_barcnt, 0u);
            __threadfence();
            atomicAdd(&g_bargen, 1u);
        } else {
            while (*(volatile unsigned*)&g_bargen == gen) __nanosleep(64);
        }
        __threadfence();
    }
    __syncthreads();
}

__device__ __forceinline__ float sigm(float v) { return 1.f / (1.f + __expf(-v)); }

// ---------------------------------------------------------------------------
// K1: fp32 GEMM with fused embedding gather (unchanged)
// ---------------------------------------------------------------------------
template <int MODE>
__global__ void __launch_bounds__(256, 2)
gemm_tn(const float* __restrict__ A, const float* __restrict__ W,
        const float* __restrict__ bias, float* __restrict__ C,
        const int* __restrict__ xidx, int N)
{
    __shared__ float As[16 * 128];
    __shared__ float Bs[16 * 128];

    const int tid  = threadIdx.x;
    const int m0   = blockIdx.y * 128;
    const int n0   = blockIdx.x * 128;
    const int lrow = tid >> 2;
    const int lk   = (tid & 3) * 4;
    const int ty   = tid >> 4;
    const int tx   = tid & 15;

    const float *ap0, *ap1;
    {
        int ma0 = m0 + lrow, ma1 = ma0 + 64;
        if (MODE == 1) {
            int r0 = xidx[(ma0 & 31) * Tc + (ma0 >> 5)];
            int r1 = xidx[(ma1 & 31) * Tc + (ma1 >> 5)];
            ap0 = A + (size_t)r0 * Hc;
            ap1 = A + (size_t)r1 * Hc;
        } else {
            ap0 = A + (size_t)ma0 * Hc;
            ap1 = A + (size_t)ma1 * Hc;
        }
    }
    const float* bp0 = W + (size_t)(n0 + lrow) * Hc;
    const float* bp1 = bp0 + (size_t)64 * Hc;

    float acc[8][8];
#pragma unroll
    for (int i = 0; i < 8; i++)
#pragma unroll
        for (int j = 0; j < 8; j++) acc[i][j] = 0.f;

    for (int kt = 0; kt < Hc; kt += 16) {
        float4 a0 = *(const float4*)(ap0 + kt + lk);
        float4 a1 = *(const float4*)(ap1 + kt + lk);
        float4 b0 = *(const float4*)(bp0 + kt + lk);
        float4 b1 = *(const float4*)(bp1 + kt + lk);
        __syncthreads();
        As[(lk + 0) * 128 + lrow]      = a0.x;
        As[(lk + 1) * 128 + lrow]      = a0.y;
        As[(lk + 2) * 128 + lrow]      = a0.z;
        As[(lk + 3) * 128 + lrow]      = a0.w;
        As[(lk + 0) * 128 + lrow + 64] = a1.x;
        As[(lk + 1) * 128 + lrow + 64] = a1.y;
        As[(lk + 2) * 128 + lrow + 64] = a1.z;
        As[(lk + 3) * 128 + lrow + 64] = a1.w;
        Bs[(lk + 0) * 128 + lrow]      = b0.x;
        Bs[(lk + 1) * 128 + lrow]      = b0.y;
        Bs[(lk + 2) * 128 + lrow]      = b0.z;
        Bs[(lk + 3) * 128 + lrow]      = b0.w;
        Bs[(lk + 0) * 128 + lrow + 64] = b1.x;
        Bs[(lk + 1) * 128 + lrow + 64] = b1.y;
        Bs[(lk + 2) * 128 + lrow + 64] = b1.z;
        Bs[(lk + 3) * 128 + lrow + 64] = b1.w;
        __syncthreads();
#pragma unroll
        for (int kk = 0; kk < 16; kk++) {
            float4 av0 = *(const float4*)&As[kk * 128 + ty * 8];
            float4 av1 = *(const float4*)&As[kk * 128 + ty * 8 + 4];
            float4 bv0 = *(const float4*)&Bs[kk * 128 + tx * 8];
            float4 bv1 = *(const float4*)&Bs[kk * 128 + tx * 8 + 4];
            float a[8] = {av0.x, av0.y, av0.z, av0.w, av1.x, av1.y, av1.z, av1.w};
            float b[8] = {bv0.x, bv0.y, bv0.z, bv0.w, bv1.x, bv1.y, bv1.z, bv1.w};
#pragma unroll
            for (int i = 0; i < 8; i++)
#pragma unroll
                for (int j = 0; j < 8; j++) acc[i][j] += a[i] * b[j];
        }
    }

    float bs[8];
#pragma unroll
    for (int j = 0; j < 8; j++) bs[j] = bias[n0 + tx * 8 + j];
#pragma unroll
    for (int i = 0; i < 8; i++) {
        size_t base = (size_t)(m0 + ty * 8 + i) * (size_t)N + n0 + tx * 8;
        float4 o0 = make_float4(acc[i][0] + bs[0], acc[i][1] + bs[1],
                                acc[i][2] + bs[2], acc[i][3] + bs[3]);
        float4 o1 = make_float4(acc[i][4] + bs[4], acc[i][5] + bs[5],
                                acc[i][6] + bs[6], acc[i][7] + bs[7]);
        *(float4*)&C[base]     = o0;
        *(float4*)&C[base + 4] = o1;
    }
}

// ---------------------------------------------------------------------------
// K2: persistent GRU recurrence (unchanged — passing since R5)
// ---------------------------------------------------------------------------
#define REC_SMEM_FLOATS (12 * 512 + 24 * 512 + 512 * 33 + 768)

__global__ void __launch_bounds__(256, 1)
gru_rec(const float* __restrict__ Wih, const float* __restrict__ Whh,
        const float* __restrict__ bih, const float* __restrict__ bhh)
{
    extern __shared__ float sm[];
    float* ws1  = sm;
    float* ws2  = sm + 12 * 512;
    float* hs   = sm + 36 * 512;
    float* psum = hs + 512 * 33;

    const int tid = threadIdx.x;
    const int bk  = blockIdx.x;
    const int j0  = bk * 4;

    const float* Whh0 = Whh;
    const float* Wih1 = Wih + 1536 * 512;
    const float* Whh1 = Whh + 1536 * 512;

    for (int idx = tid; idx < 12 * 512; idx += 256) {
        int rl = idx >> 9, k = idx & 511;
        int jj = rl / 3, g = rl % 3;
        ws1[idx] = Whh0[(size_t)(g * Hc + j0 + jj) * Hc + k];
    }
    for (int idx = tid; idx < 24 * 512; idx += 256) {
        int rl = idx >> 9, k = idx & 511;
        int jj = rl / 6, g = rl % 6;
        const float* src = (g < 3) ? Wih1 : Whh1;
        int gg = (g < 3) ? g : g - 3;
        ws2[idx] = src[(size_t)(gg * Hc + j0 + jj) * Hc + k];
    }
    {
        int i = bk * 256 + tid;
        if (i < Bc * Hc) g_h[i] = 0.f;
    }

    const int out = tid & 127;
    const int b   = out & 31;
    const int jj  = out >> 5;
    const int kh  = tid >> 7;
    const int j   = j0 + jj;

    const float bhh0r = bhh[j],          bhh0z = bhh[Hc + j],          bhh0n = bhh[2 * Hc + j];
    const float bih1r = bih[3 * Hc + j], bih1z = bih[4 * Hc + j],      bih1n = bih[5 * Hc + j];
    const float bhh1r = bhh[3 * Hc + j], bhh1z = bhh[4 * Hc + j],      bhh1n = bhh[5 * Hc + j];

    gridbar();

    for (int t = 0; t < Tc; t++) {
        for (int i = tid; i < Bc * Hc; i += 256) {
            int bb = i >> 9, k = i & 511;
            hs[k * 33 + bb] = __ldcg(&g_h[i]);
        }
        __syncthreads();
        {
            const float* wr = ws1 + (jj * 3) * Hc + kh * 256;
            const float* wz = wr + Hc;
            const float* wn = wz + Hc;
            const float* hp = hs + (kh * 256) * 33 + b;
            float sr = 0.f, sz = 0.f, sn = 0.f;
#pragma unroll 8
            for (int k = 0; k < 256; k += 4) {
                float4 vr = *(const float4*)(wr + k);
                float4 vz = *(const float4*)(wz + k);
                float4 vn = *(const float4*)(wn + k);
                float h0 = hp[(k + 0) * 33], h1v = hp[(k + 1) * 33];
                float h2 = hp[(k + 2) * 33], h3v = hp[(k + 3) * 33];
                sr += vr.x * h0 + vr.y * h1v + vr.z * h2 + vr.w * h3v;
                sz += vz.x * h0 + vz.y * h1v + vz.z * h2 + vz.w * h3v;
                sn += vn.x * h0 + vn.y * h1v + vn.z * h2 + vn.w * h3v;
            }
            if (kh) { psum[out * 3 + 0] = sr; psum[out * 3 + 1] = sz; psum[out * 3 + 2] = sn; }
            __syncthreads();
            if (!kh) {
                sr += psum[out * 3 + 0]; sz += psum[out * 3 + 1]; sn += psum[out * 3 + 2];
                const float* gi = g_gi0 + (size_t)(t * Bc + b) * 1536;
                float r = sigm(gi[j] + sr + bhh0r);
                float z = sigm(gi[Hc + j] + sz + bhh0z);
                float n = tanhf(gi[2 * Hc + j] + r * (sn + bhh0n));
                float hprev = hs[j * 33 + b];
                g_h1[b * Hc + j] = (1.f - z) * n + z * hprev;
            }
        }
        gridbar();

        for (int i = tid; i < Bc * Hc; i += 256) {
            int bb = i >> 9, k = i & 511;
            hs[k * 33 + bb] = __ldcg(&g_h1[i]);
        }
        __syncthreads();
        {
            const float* w0 = ws2 + (jj * 6) * Hc + kh * 256;
            const float* hp = hs + (kh * 256) * 33 + b;
            float s0 = 0.f, s1 = 0.f, s2 = 0.f, s3 = 0.f, s4 = 0.f, s5 = 0.f;
#pragma unroll 4
            for (int k = 0; k < 256; k += 4) {
                float4 v0 = *(const float4*)(w0 + k);
                float4 v1 = *(const float4*)(w0 + Hc + k);
                float4 v2 = *(const float4*)(w0 + 2 * Hc + k);
                float4 v3 = *(const float4*)(w0 + 3 * Hc + k);
                float4 v4 = *(const float4*)(w0 + 4 * Hc + k);
                float4 v5 = *(const float4*)(w0 + 5 * Hc + k);
                float h0 = hp[(k + 0) * 33], h1v = hp[(k + 1) * 33];
                float h2 = hp[(k + 2) * 33], h3v = hp[(k + 3) * 33];
                s0 += v0.x * h0 + v0.y * h1v + v0.z * h2 + v0.w * h3v;
                s1 += v1.x * h0 + v1.y * h1v + v1.z * h2 + v1.w * h3v;
                s2 += v2.x * h0 + v2.y * h1v + v2.z * h2 + v2.w * h3v;
                s3 += v3.x * h0 + v3.y * h1v + v3.z * h2 + v3.w * h3v;
                s4 += v4.x * h0 + v4.y * h1v + v4.z * h2 + v4.w * h3v;
                s5 += v5.x * h0 + v5.y * h1v + v5.z * h2 + v5.w * h3v;
            }
            if (kh) {
                psum[out * 6 + 0] = s0; psum[out * 6 + 1] = s1; psum[out * 6 + 2] = s2;
                psum[out * 6 + 3] = s3; psum[out * 6 + 4] = s4; psum[out * 6 + 5] = s5;
            }
            __syncthreads();
            if (!kh) {
                s0 += psum[out * 6 + 0]; s1 += psum[out * 6 + 1]; s2 += psum[out * 6 + 2];
                s3 += psum[out * 6 + 3]; s4 += psum[out * 6 + 4]; s5 += psum[out * 6 + 5];
                float r = sigm((s0 + bih1r) + (s3 + bhh1r));
                float z = sigm((s1 + bih1z) + (s4 + bhh1z));
                float n = tanhf((s2 + bih1n) + r * (s5 + bhh1n));
                float h1v = hs[j * 33 + b];
                float h2 = (1.f - z) * n + z * h1v;
                g_h[b * Hc + j] = h2;
                g_outs[(size_t)(b * Tc + t) * Hc + j] = h2;
            }
        }
        gridbar();
    }
}

// ---------------------------------------------------------------------------
// fp16 2-term conversion kernels
// A' row m: [hi | lo]  (exact to 2^-22)
// B' row n: [hi | hi]  (residual error = B rounding only, ~2^-12 RMS)
// ---------------------------------------------------------------------------
__global__ void conv_a() {
    int i = blockIdx.x * 256 + threadIdx.x;
    if (i >= Bc * Tc * Hc) return;
    int m = i >> 9, k = i & 511;
    float x = g_outs[i];
    __half hi = __float2half_rn(x);
    __half lo = __float2half_rn(x - __half2float(hi));
    size_t base = (size_t)m * GKB + k;
    g_abf[base]       = hi;
    g_abf[base + 512] = lo;
}

__global__ void conv_b(const float* __restrict__ Wout) {
    int i = blockIdx.x * 256 + threadIdx.x;
    if (i >= Vc * Hc) return;
    int n = i >> 9, k = i & 511;
    __half hi = __float2half_rn(Wout[i]);
    size_t base = (size_t)n * GKB + k;
    g_bbf[base]       = hi;
    g_bbf[base + 512] = hi;
}

// ---------------------------------------------------------------------------
// K3: HMMA fp16 GEMM, CTA tile 128x128, warp tile 32x64 (R9-verified layout),
// 4-stage cp.async pipeline, ONE __syncthreads per K32 chunk, 2 CTAs/SM.
// Stage: [A 128 rows | B 128 rows] x SROW bytes.
// ---------------------------------------------------------------------------
__global__ void __launch_bounds__(256, 2)
gemm_hmma(const float* __restrict__ bout, float* __restrict__ C)
{
    extern __shared__ __align__(16) char smc[];
    const uint32_t sb = smem_u32(smc);
    const int tid  = threadIdx.x;
    const int lane = tid & 31;
    const int wid  = tid >> 5;
    const int wm   = wid & 3;            // 4 warps in M (R9 layout)
    const int wn   = wid >> 2;           // 2 warps in N
    const int m0   = blockIdx.x * 128;   // m fastest: A' (16MB) L2-resident
    const int n0   = blockIdx.y * 128;

    const __half* Ag = g_abf + (size_t)m0 * GKB;
    const __half* Bg = g_bbf + (size_t)n0 * GKB;

    float acc[2][8][4];
#pragma unroll
    for (int mb = 0; mb < 2; mb++)
#pragma unroll
        for (int nb = 0; nb < 8; nb++)
#pragma unroll
            for (int q = 0; q < 4; q++) acc[mb][nb][q] = 0.f;

    // chunk loader: A 128 rows + B 128 rows, 4 x 16B segs per row (64B data)
    auto load_chunk = [&](int c) {
        const uint32_t stg = sb + (uint32_t)(c & 3) * STG_BYTES;
        const int kc = c * KCH;
#pragma unroll
        for (int r = 0; r < 2; r++) {                 // A: 512 segs
            int seg = tid + r * 256;
            int row = seg >> 2, i = seg & 3;
            CP16(stg + (uint32_t)(row * SROW + i * 16),
                 Ag + (size_t)row * GKB + kc + i * 8);
        }
        const uint32_t stgB = stg + 128 * SROW;
#pragma unroll
        for (int r = 0; r < 2; r++) {                 // B: 512 segs
            int seg = tid + r * 256;
            int row = seg >> 2, i = seg & 3;
            CP16(stgB + (uint32_t)(row * SROW + i * 16),
                 Bg + (size_t)row * GKB + kc + i * 8);
        }
    };

    load_chunk(0); CP_COMMIT();
    load_chunk(1); CP_COMMIT();
    load_chunk(2); CP_COMMIT();

    for (int c = 0; c < NCHUNK; c++) {
        CP_WAIT(2);                 // chunk c landed (c+1, c+2 may be in flight)
        __syncthreads();            // all warps done reading stage (c-1)&3

        if (c + 3 < NCHUNK) load_chunk(c + 3);   // stage (c-1)&3, overlaps MMAs
        CP_COMMIT();                              // uniform group accounting

        const uint32_t aB = sb + (uint32_t)(c & 3) * STG_BYTES;
        const uint32_t bB = aB + 128 * SROW;

#pragma unroll
        for (int kk = 0; kk < 2; kk++) {      // two k16 steps per 32-chunk
            uint32_t a[2][4];
            {
                uint32_t addr = aB + (uint32_t)((wm * 32 + (lane & 15)) * SROW
                                  + (kk * 16 + ((lane >> 4) << 3)) * 2);
                LDSM4(a[0][0], a[0][1], a[0][2], a[0][3], addr);
                LDSM4(a[1][0], a[1][1], a[1][2], a[1][3], addr + 16 * SROW);
            }
            uint32_t b[8][2];
            {
                const int q = lane >> 3, rr = lane & 7;
                const int nbase = wn * 64 + ((q & 2) << 2) + rr;   // +8 for q>=2
                const int kcol  = kk * 16 + ((q & 1) << 3);
#pragma unroll
                for (int p = 0; p < 4; p++) {
                    uint32_t addr = bB + (uint32_t)((nbase + p * 16) * SROW + kcol * 2);
                    LDSM4(b[2 * p][0], b[2 * p][1], b[2 * p + 1][0], b[2 * p + 1][1], addr);
                }
            }
#pragma unroll
            for (int mb = 0; mb < 2; mb++)
#pragma unroll
                for (int nb = 0; nb < 8; nb++)
                    MMA16816(acc[mb][nb], a[mb], b[nb]);
        }
    }

    // epilogue: d-frag (m16n8): rows lane>>2 (+8), cols (lane&3)*2
#pragma unroll
    for (int mb = 0; mb < 2; mb++) {
        const int row = m0 + wm * 32 + mb * 16 + (lane >> 2);
#pragma unroll
        for (int nb = 0; nb < 8; nb++) {
            const int col = n0 + wn * 64 + nb * 8 + (lane & 3) * 2;
            const float b0 = __ldg(&bout[col]);
            const float b1 = __ldg(&bout[col + 1]);
            float2 o0 = make_float2(acc[mb][nb][0] + b0, acc[mb][nb][1] + b1);
            float2 o1 = make_float2(acc[mb][nb][2] + b0, acc[mb][nb][3] + b1);
            *(float2*)&C[(size_t)row * Vc + col]       = o0;
            *(float2*)&C[(size_t)(row + 8) * Vc + col] = o1;
        }
    }
}

// ---------------------------------------------------------------------------
// Launch
// ---------------------------------------------------------------------------
extern "C" void kernel_launch(void* const* d_in, const int* in_sizes, int n_in,
                              void* d_out, int out_size)
{
    const int*   x    = (const int*)d_in[0];
    const float* emb  = (const float*)d_in[1];
    const float* Wih  = (const float*)d_in[2];
    const float* Whh  = (const float*)d_in[3];
    const float* bih  = (const float*)d_in[4];
    const float* bhh  = (const float*)d_in[5];
    const float* Wout = (const float*)d_in[6];
    const float* bout = (const float*)d_in[7];
    float* out = (float*)d_out;

    void* p;
    cudaGetSymbolAddress(&p, g_gi0);  float* gi0 = (float*)p;

    // K1: gi0[t*32+b][0:1536] = emb[x[b][t]] @ Wih0^T + bih0
    dim3 g1(1536 / 128, (Bc * Tc) / 128);
    gemm_tn<1><<<g1, 256>>>(emb, Wih, bih, gi0, x, 1536);

    // B' fp16 conversion (independent of recurrence)
    conv_b<<<(Vc * Hc + 255) / 256, 256>>>(Wout);

    // K2: persistent recurrence
    size_t smem = REC_SMEM_FLOATS * sizeof(float);
    cudaFuncSetAttribute(gru_rec, cudaFuncAttributeMaxDynamicSharedMemorySize, (int)smem);
    gru_rec<<<NBLK, 256, smem>>>(Wih, Whh, bih, bhh);

    // A' fp16 conversion (needs g_outs)
    conv_a<<<(Bc * Tc * Hc + 255) / 256, 256>>>();

    // K3: logits = A' @ B'^T + bout via mma.sync fp16 (2-term, K'=1024)
    cudaFuncSetAttribute(gemm_hmma, cudaFuncAttributeMaxDynamicSharedMemorySize, TC_SMEM);
    dim3 g3((Bc * Tc) / 128, Vc / 128);   // (64, 250), m fastest
    gemm_hmma<<<g3, 256, TC_SMEM>>>(bout, out);
}

// round 15
// speedup vs baseline: 1.2834x; 1.1082x over previous
#include <cuda_runtime.h>
#include <cuda_fp16.h>
#include <cstdint>

// Problem constants
#define Bc 32
#define Tc 256
#define Hc 512
#define Vc 32000
#define NBLK 128   // persistent recurrence grid (1 block/SM => co-resident)

// K3 GEMM constants (plain fp16, K=512)
#define GKB 512             // K (no split terms)
#define KCH 32              // fp16 per K chunk (64B row)
#define NCHUNK (GKB / KCH)  // 16
#define SROW 80             // SMEM row stride bytes -> ldmatrix conflict-free
#define NSTG 4
#define STG_BYTES ((128 + 128) * SROW)   // A(128)+B(128) rows = 20480
#define TC_SMEM (NSTG * STG_BYTES)       // 81920 (2 CTAs/SM: 163840 < 228KB)

// ---------------------------------------------------------------------------
// Scratch (device globals: allocation-free per harness rules)
// ---------------------------------------------------------------------------
__device__ float g_gi0[Tc * Bc * 3 * Hc];
__device__ float g_outs[Bc * Tc * Hc];
__device__ float g_h[Bc * Hc];
__device__ float g_h1[Bc * Hc];
__device__ unsigned g_barcnt;
__device__ unsigned g_bargen;
__device__ __half g_abf[(size_t)Bc * Tc * GKB];   // [8192][512] fp16(A)
__device__ __half g_bbf[(size_t)Vc * GKB];        // [32000][512] fp16(B)

// ---------------------------------------------------------------------------
// Baseline-ISA PTX helpers (sm_80+ only; NO 'a'-suffix instructions)
// ---------------------------------------------------------------------------
__device__ __forceinline__ uint32_t smem_u32(const void* p) {
    uint32_t a;
    asm("{ .reg .u64 t; cvta.to.shared.u64 t, %1; cvt.u32.u64 %0, t; }"
        : "=r"(a) : "l"(p));
    return a;
}

#define CP16(dst, src) \
    asm volatile("cp.async.cg.shared.global [%0], [%1], 16;" \
                 :: "r"(dst), "l"(src))
#define CP_COMMIT() asm volatile("cp.async.commit_group;" ::: "memory")
#define CP_WAIT(n)  asm volatile("cp.async.wait_group %0;" :: "n"(n) : "memory")

#define LDSM4(r0, r1, r2, r3, addr) \
    asm volatile("ldmatrix.sync.aligned.m8n8.x4.shared.b16 {%0,%1,%2,%3}, [%4];" \
                 : "=r"(r0), "=r"(r1), "=r"(r2), "=r"(r3) : "r"(addr))

#define MMA16816(d, a, b) \
    asm volatile("mma.sync.aligned.m16n8k16.row.col.f32.f16.f16.f32 " \
                 "{%0,%1,%2,%3}, {%4,%5,%6,%7}, {%8,%9}, {%0,%1,%2,%3};" \
                 : "+f"((d)[0]), "+f"((d)[1]), "+f"((d)[2]), "+f"((d)[3]) \
                 : "r"((a)[0]), "r"((a)[1]), "r"((a)[2]), "r"((a)[3]), \
                   "r"((b)[0]), "r"((b)[1]))

// ---------------------------------------------------------------------------
// Grid barrier for the recurrence kernel
// ---------------------------------------------------------------------------
__device__ __forceinline__ void gridbar() {
    __syncthreads();
    if (threadIdx.x == 0) {
        __threadfence();
        unsigned gen = *(volatile unsigned*)&g_bargen;
        if (atomicAdd(&g_barcnt, 1u) == NBLK - 1) {
            atomicExch(&g_barcnt, 0u);
            __threadfence();
            atomicAdd(&g_bargen, 1u);
        } else {
            while (*(volatile unsigned*)&g_bargen == gen) __nanosleep(64);
        }
        __threadfence();
    }
    __syncthreads();
}

__device__ __forceinline__ float sigm(float v) { return 1.f / (1.f + __expf(-v)); }

// ---------------------------------------------------------------------------
// K1: fp32 GEMM with fused embedding gather (unchanged)
// ---------------------------------------------------------------------------
template <int MODE>
__global__ void __launch_bounds__(256, 2)
gemm_tn(const float* __restrict__ A, const float* __restrict__ W,
        const float* __restrict__ bias, float* __restrict__ C,
        const int* __restrict__ xidx, int N)
{
    __shared__ float As[16 * 128];
    __shared__ float Bs[16 * 128];

    const int tid  = threadIdx.x;
    const int m0   = blockIdx.y * 128;
    const int n0   = blockIdx.x * 128;
    const int lrow = tid >> 2;
    const int lk   = (tid & 3) * 4;
    const int ty   = tid >> 4;
    const int tx   = tid & 15;

    const float *ap0, *ap1;
    {
        int ma0 = m0 + lrow, ma1 = ma0 + 64;
        if (MODE == 1) {
            int r0 = xidx[(ma0 & 31) * Tc + (ma0 >> 5)];
            int r1 = xidx[(ma1 & 31) * Tc + (ma1 >> 5)];
            ap0 = A + (size_t)r0 * Hc;
            ap1 = A + (size_t)r1 * Hc;
        } else {
            ap0 = A + (size_t)ma0 * Hc;
            ap1 = A + (size_t)ma1 * Hc;
        }
    }
    const float* bp0 = W + (size_t)(n0 + lrow) * Hc;
    const float* bp1 = bp0 + (size_t)64 * Hc;

    float acc[8][8];
#pragma unroll
    for (int i = 0; i < 8; i++)
#pragma unroll
        for (int j = 0; j < 8; j++) acc[i][j] = 0.f;

    for (int kt = 0; kt < Hc; kt += 16) {
        float4 a0 = *(const float4*)(ap0 + kt + lk);
        float4 a1 = *(const float4*)(ap1 + kt + lk);
        float4 b0 = *(const float4*)(bp0 + kt + lk);
        float4 b1 = *(const float4*)(bp1 + kt + lk);
        __syncthreads();
        As[(lk + 0) * 128 + lrow]      = a0.x;
        As[(lk + 1) * 128 + lrow]      = a0.y;
        As[(lk + 2) * 128 + lrow]      = a0.z;
        As[(lk + 3) * 128 + lrow]      = a0.w;
        As[(lk + 0) * 128 + lrow + 64] = a1.x;
        As[(lk + 1) * 128 + lrow + 64] = a1.y;
        As[(lk + 2) * 128 + lrow + 64] = a1.z;
        As[(lk + 3) * 128 + lrow + 64] = a1.w;
        Bs[(lk + 0) * 128 + lrow]      = b0.x;
        Bs[(lk + 1) * 128 + lrow]      = b0.y;
        Bs[(lk + 2) * 128 + lrow]      = b0.z;
        Bs[(lk + 3) * 128 + lrow]      = b0.w;
        Bs[(lk + 0) * 128 + lrow + 64] = b1.x;
        Bs[(lk + 1) * 128 + lrow + 64] = b1.y;
        Bs[(lk + 2) * 128 + lrow + 64] = b1.z;
        Bs[(lk + 3) * 128 + lrow + 64] = b1.w;
        __syncthreads();
#pragma unroll
        for (int kk = 0; kk < 16; kk++) {
            float4 av0 = *(const float4*)&As[kk * 128 + ty * 8];
            float4 av1 = *(const float4*)&As[kk * 128 + ty * 8 + 4];
            float4 bv0 = *(const float4*)&Bs[kk * 128 + tx * 8];
            float4 bv1 = *(const float4*)&Bs[kk * 128 + tx * 8 + 4];
            float a[8] = {av0.x, av0.y, av0.z, av0.w, av1.x, av1.y, av1.z, av1.w};
            float b[8] = {bv0.x, bv0.y, bv0.z, bv0.w, bv1.x, bv1.y, bv1.z, bv1.w};
#pragma unroll
            for (int i = 0; i < 8; i++)
#pragma unroll
                for (int j = 0; j < 8; j++) acc[i][j] += a[i] * b[j];
        }
    }

    float bs[8];
#pragma unroll
    for (int j = 0; j < 8; j++) bs[j] = bias[n0 + tx * 8 + j];
#pragma unroll
    for (int i = 0; i < 8; i++) {
        size_t base = (size_t)(m0 + ty * 8 + i) * (size_t)N + n0 + tx * 8;
        float4 o0 = make_float4(acc[i][0] + bs[0], acc[i][1] + bs[1],
                                acc[i][2] + bs[2], acc[i][3] + bs[3]);
        float4 o1 = make_float4(acc[i][4] + bs[4], acc[i][5] + bs[5],
                                acc[i][6] + bs[6], acc[i][7] + bs[7]);
        *(float4*)&C[base]     = o0;
        *(float4*)&C[base + 4] = o1;
    }
}

// ---------------------------------------------------------------------------
// K2: persistent GRU recurrence (unchanged — passing since R5)
// ---------------------------------------------------------------------------
#define REC_SMEM_FLOATS (12 * 512 + 24 * 512 + 512 * 33 + 768)

__global__ void __launch_bounds__(256, 1)
gru_rec(const float* __restrict__ Wih, const float* __restrict__ Whh,
        const float* __restrict__ bih, const float* __restrict__ bhh)
{
    extern __shared__ float sm[];
    float* ws1  = sm;
    float* ws2  = sm + 12 * 512;
    float* hs   = sm + 36 * 512;
    float* psum = hs + 512 * 33;

    const int tid = threadIdx.x;
    const int bk  = blockIdx.x;
    const int j0  = bk * 4;

    const float* Whh0 = Whh;
    const float* Wih1 = Wih + 1536 * 512;
    const float* Whh1 = Whh + 1536 * 512;

    for (int idx = tid; idx < 12 * 512; idx += 256) {
        int rl = idx >> 9, k = idx & 511;
        int jj = rl / 3, g = rl % 3;
        ws1[idx] = Whh0[(size_t)(g * Hc + j0 + jj) * Hc + k];
    }
    for (int idx = tid; idx < 24 * 512; idx += 256) {
        int rl = idx >> 9, k = idx & 511;
        int jj = rl / 6, g = rl % 6;
        const float* src = (g < 3) ? Wih1 : Whh1;
        int gg = (g < 3) ? g : g - 3;
        ws2[idx] = src[(size_t)(gg * Hc + j0 + jj) * Hc + k];
    }
    {
        int i = bk * 256 + tid;
        if (i < Bc * Hc) g_h[i] = 0.f;
    }

    const int out = tid & 127;
    const int b   = out & 31;
    const int jj  = out >> 5;
    const int kh  = tid >> 7;
    const int j   = j0 + jj;

    const float bhh0r = bhh[j],          bhh0z = bhh[Hc + j],          bhh0n = bhh[2 * Hc + j];
    const float bih1r = bih[3 * Hc + j], bih1z = bih[4 * Hc + j],      bih1n = bih[5 * Hc + j];
    const float bhh1r = bhh[3 * Hc + j], bhh1z = bhh[4 * Hc + j],      bhh1n = bhh[5 * Hc + j];

    gridbar();

    for (int t = 0; t < Tc; t++) {
        for (int i = tid; i < Bc * Hc; i += 256) {
            int bb = i >> 9, k = i & 511;
            hs[k * 33 + bb] = __ldcg(&g_h[i]);
        }
        __syncthreads();
        {
            const float* wr = ws1 + (jj * 3) * Hc + kh * 256;
            const float* wz = wr + Hc;
            const float* wn = wz + Hc;
            const float* hp = hs + (kh * 256) * 33 + b;
            float sr = 0.f, sz = 0.f, sn = 0.f;
#pragma unroll 8
            for (int k = 0; k < 256; k += 4) {
                float4 vr = *(const float4*)(wr + k);
                float4 vz = *(const float4*)(wz + k);
                float4 vn = *(const float4*)(wn + k);
                float h0 = hp[(k + 0) * 33], h1v = hp[(k + 1) * 33];
                float h2 = hp[(k + 2) * 33], h3v = hp[(k + 3) * 33];
                sr += vr.x * h0 + vr.y * h1v + vr.z * h2 + vr.w * h3v;
                sz += vz.x * h0 + vz.y * h1v + vz.z * h2 + vz.w * h3v;
                sn += vn.x * h0 + vn.y * h1v + vn.z * h2 + vn.w * h3v;
            }
            if (kh) { psum[out * 3 + 0] = sr; psum[out * 3 + 1] = sz; psum[out * 3 + 2] = sn; }
            __syncthreads();
            if (!kh) {
                sr += psum[out * 3 + 0]; sz += psum[out * 3 + 1]; sn += psum[out * 3 + 2];
                const float* gi = g_gi0 + (size_t)(t * Bc + b) * 1536;
                float r = sigm(gi[j] + sr + bhh0r);
                float z = sigm(gi[Hc + j] + sz + bhh0z);
                float n = tanhf(gi[2 * Hc + j] + r * (sn + bhh0n));
                float hprev = hs[j * 33 + b];
                g_h1[b * Hc + j] = (1.f - z) * n + z * hprev;
            }
        }
        gridbar();

        for (int i = tid; i < Bc * Hc; i += 256) {
            int bb = i >> 9, k = i & 511;
            hs[k * 33 + bb] = __ldcg(&g_h1[i]);
        }
        __syncthreads();
        {
            const float* w0 = ws2 + (jj * 6) * Hc + kh * 256;
            const float* hp = hs + (kh * 256) * 33 + b;
            float s0 = 0.f, s1 = 0.f, s2 = 0.f, s3 = 0.f, s4 = 0.f, s5 = 0.f;
#pragma unroll 4
            for (int k = 0; k < 256; k += 4) {
                float4 v0 = *(const float4*)(w0 + k);
                float4 v1 = *(const float4*)(w0 + Hc + k);
                float4 v2 = *(const float4*)(w0 + 2 * Hc + k);
                float4 v3 = *(const float4*)(w0 + 3 * Hc + k);
                float4 v4 = *(const float4*)(w0 + 4 * Hc + k);
                float4 v5 = *(const float4*)(w0 + 5 * Hc + k);
                float h0 = hp[(k + 0) * 33], h1v = hp[(k + 1) * 33];
                float h2 = hp[(k + 2) * 33], h3v = hp[(k + 3) * 33];
                s0 += v0.x * h0 + v0.y * h1v + v0.z * h2 + v0.w * h3v;
                s1 += v1.x * h0 + v1.y * h1v + v1.z * h2 + v1.w * h3v;
                s2 += v2.x * h0 + v2.y * h1v + v2.z * h2 + v2.w * h3v;
                s3 += v3.x * h0 + v3.y * h1v + v3.z * h2 + v3.w * h3v;
                s4 += v4.x * h0 + v4.y * h1v + v4.z * h2 + v4.w * h3v;
                s5 += v5.x * h0 + v5.y * h1v + v5.z * h2 + v5.w * h3v;
            }
            if (kh) {
                psum[out * 6 + 0] = s0; psum[out * 6 + 1] = s1; psum[out * 6 + 2] = s2;
                psum[out * 6 + 3] = s3; psum[out * 6 + 4] = s4; psum[out * 6 + 5] = s5;
            }
            __syncthreads();
            if (!kh) {
                s0 += psum[out * 6 + 0]; s1 += psum[out * 6 + 1]; s2 += psum[out * 6 + 2];
                s3 += psum[out * 6 + 3]; s4 += psum[out * 6 + 4]; s5 += psum[out * 6 + 5];
                float r = sigm((s0 + bih1r) + (s3 + bhh1r));
                float z = sigm((s1 + bih1z) + (s4 + bhh1z));
                float n = tanhf((s2 + bih1n) + r * (s5 + bhh1n));
                float h1v = hs[j * 33 + b];
                float h2 = (1.f - z) * n + z * h1v;
                g_h[b * Hc + j] = h2;
                g_outs[(size_t)(b * Tc + t) * Hc + j] = h2;
            }
        }
        gridbar();
    }
}

// ---------------------------------------------------------------------------
// fp16 conversion kernels (plain rounding, K=512)
// ---------------------------------------------------------------------------
__global__ void conv_a() {
    int i = blockIdx.x * 256 + threadIdx.x;
    if (i >= Bc * Tc * Hc) return;
    g_abf[i] = __float2half_rn(g_outs[i]);
}

__global__ void conv_b(const float* __restrict__ Wout) {
    int i = blockIdx.x * 256 + threadIdx.x;
    if (i >= Vc * Hc) return;
    g_bbf[i] = __float2half_rn(Wout[i]);
}

// ---------------------------------------------------------------------------
// K3: HMMA fp16 GEMM, CTA tile 128x128, warp tile 32x64 (R9-verified layout),
// 4-stage cp.async pipeline, ONE __syncthreads per K32 chunk, 2 CTAs/SM.
// Stage: [A 128 rows | B 128 rows] x SROW bytes.
// ---------------------------------------------------------------------------
__global__ void __launch_bounds__(256, 2)
gemm_hmma(const float* __restrict__ bout, float* __restrict__ C)
{
    extern __shared__ __align__(16) char smc[];
    const uint32_t sb = smem_u32(smc);
    const int tid  = threadIdx.x;
    const int lane = tid & 31;
    const int wid  = tid >> 5;
    const int wm   = wid & 3;            // 4 warps in M (R9 layout)
    const int wn   = wid >> 2;           // 2 warps in N
    const int m0   = blockIdx.x * 128;   // m fastest: A' (8MB) L2-resident
    const int n0   = blockIdx.y * 128;

    const __half* Ag = g_abf + (size_t)m0 * GKB;
    const __half* Bg = g_bbf + (size_t)n0 * GKB;

    float acc[2][8][4];
#pragma unroll
    for (int mb = 0; mb < 2; mb++)
#pragma unroll
        for (int nb = 0; nb < 8; nb++)
#pragma unroll
            for (int q = 0; q < 4; q++) acc[mb][nb][q] = 0.f;

    // chunk loader: A 128 rows + B 128 rows, 4 x 16B segs per row (64B data)
    auto load_chunk = [&](int c) {
        const uint32_t stg = sb + (uint32_t)(c & 3) * STG_BYTES;
        const int kc = c * KCH;
#pragma unroll
        for (int r = 0; r < 2; r++) {                 // A: 512 segs
            int seg = tid + r * 256;
            int row = seg >> 2, i = seg & 3;
            CP16(stg + (uint32_t)(row * SROW + i * 16),
                 Ag + (size_t)row * GKB + kc + i * 8);
        }
        const uint32_t stgB = stg + 128 * SROW;
#pragma unroll
        for (int r = 0; r < 2; r++) {                 // B: 512 segs
            int seg = tid + r * 256;
            int row = seg >> 2, i = seg & 3;
            CP16(stgB + (uint32_t)(row * SROW + i * 16),
                 Bg + (size_t)row * GKB + kc + i * 8);
        }
    };

    load_chunk(0); CP_COMMIT();
    load_chunk(1); CP_COMMIT();
    load_chunk(2); CP_COMMIT();

    for (int c = 0; c < NCHUNK; c++) {
        CP_WAIT(2);                 // chunk c landed (c+1, c+2 may be in flight)
        __syncthreads();            // all warps done reading stage (c-1)&3

        if (c + 3 < NCHUNK) load_chunk(c + 3);   // stage (c-1)&3, overlaps MMAs
        CP_COMMIT();                              // uniform group accounting

        const uint32_t aB = sb + (uint32_t)(c & 3) * STG_BYTES;
        const uint32_t bB = aB + 128 * SROW;

#pragma unroll
        for (int kk = 0; kk < 2; kk++) {      // two k16 steps per 32-chunk
            uint32_t a[2][4];
            {
                uint32_t addr = aB + (uint32_t)((wm * 32 + (lane & 15)) * SROW
                                  + (kk * 16 + ((lane >> 4) << 3)) * 2);
                LDSM4(a[0][0], a[0][1], a[0][2], a[0][3], addr);
                LDSM4(a[1][0], a[1][1], a[1][2], a[1][3], addr + 16 * SROW);
            }
            uint32_t b[8][2];
            {
                const int q = lane >> 3, rr = lane & 7;
                const int nbase = wn * 64 + ((q & 2) << 2) + rr;   // +8 for q>=2
                const int kcol  = kk * 16 + ((q & 1) << 3);
#pragma unroll
                for (int p = 0; p < 4; p++) {
                    uint32_t addr = bB + (uint32_t)((nbase + p * 16) * SROW + kcol * 2);
                    LDSM4(b[2 * p][0], b[2 * p][1], b[2 * p + 1][0], b[2 * p + 1][1], addr);
                }
            }
#pragma unroll
            for (int mb = 0; mb < 2; mb++)
#pragma unroll
                for (int nb = 0; nb < 8; nb++)
                    MMA16816(acc[mb][nb], a[mb], b[nb]);
        }
    }

    // epilogue: d-frag (m16n8): rows lane>>2 (+8), cols (lane&3)*2
#pragma unroll
    for (int mb = 0; mb < 2; mb++) {
        const int row = m0 + wm * 32 + mb * 16 + (lane >> 2);
#pragma unroll
        for (int nb = 0; nb < 8; nb++) {
            const int col = n0 + wn * 64 + nb * 8 + (lane & 3) * 2;
            const float b0 = __ldg(&bout[col]);
            const float b1 = __ldg(&bout[col + 1]);
            float2 o0 = make_float2(acc[mb][nb][0] + b0, acc[mb][nb][1] + b1);
            float2 o1 = make_float2(acc[mb][nb][2] + b0, acc[mb][nb][3] + b1);
            *(float2*)&C[(size_t)row * Vc + col]       = o0;
            *(float2*)&C[(size_t)(row + 8) * Vc + col] = o1;
        }
    }
}

// ---------------------------------------------------------------------------
// Launch
// ---------------------------------------------------------------------------
extern "C" void kernel_launch(void* const* d_in, const int* in_sizes, int n_in,
                              void* d_out, int out_size)
{
    const int*   x    = (const int*)d_in[0];
    const float* emb  = (const float*)d_in[1];
    const float* Wih  = (const float*)d_in[2];
    const float* Whh  = (const float*)d_in[3];
    const float* bih  = (const float*)d_in[4];
    const float* bhh  = (const float*)d_in[5];
    const float* Wout = (const float*)d_in[6];
    const float* bout = (const float*)d_in[7];
    float* out = (float*)d_out;

    void* p;
    cudaGetSymbolAddress(&p, g_gi0);  float* gi0 = (float*)p;

    // K1: gi0[t*32+b][0:1536] = emb[x[b][t]] @ Wih0^T + bih0
    dim3 g1(1536 / 128, (Bc * Tc) / 128);
    gemm_tn<1><<<g1, 256>>>(emb, Wih, bih, gi0, x, 1536);

    // B fp16 conversion (independent of recurrence)
    conv_b<<<(Vc * Hc + 255) / 256, 256>>>(Wout);

    // K2: persistent recurrence
    size_t smem = REC_SMEM_FLOATS * sizeof(float);
    cudaFuncSetAttribute(gru_rec, cudaFuncAttributeMaxDynamicSharedMemorySize, (int)smem);
    gru_rec<<<NBLK, 256, smem>>>(Wih, Whh, bih, bhh);

    // A fp16 conversion (needs g_outs)
    conv_a<<<(Bc * Tc * Hc + 255) / 256, 256>>>();

    // K3: logits = A @ B^T + bout via mma.sync fp16 (K=512)
    cudaFuncSetAttribute(gemm_hmma, cudaFuncAttributeMaxDynamicSharedMemorySize, TC_SMEM);
    dim3 g3((Bc * Tc) / 128, Vc / 128);   // (64, 250), m fastest
    gemm_hmma<<<g3, 256, TC_SMEM>>>(bout, out);
}

// round 16
// speedup vs baseline: 1.4422x; 1.1237x over previous
#include <cuda_runtime.h>
#include <cuda_fp16.h>
#include <cstdint>

// Problem constants
#define Bc 32
#define Tc 256
#define Hc 512
#define Vc 32000
#define NBLK 128   // persistent recurrence grid (1 block/SM => co-resident)

// K3 GEMM constants (plain fp16, K=512)
#define GKB 512             // K (no split terms)
#define KCH 32              // fp16 per K chunk (64B row)
#define NCHUNK (GKB / KCH)  // 16
#define SROW 80             // SMEM row stride bytes -> ldmatrix conflict-free
#define NSTG 4
#define STG_BYTES ((128 + 128) * SROW)   // A(128)+B(128) rows = 20480
#define TC_SMEM (NSTG * STG_BYTES)       // 81920 (2 CTAs/SM: 163840 < 228KB)

// ---------------------------------------------------------------------------
// Scratch (device globals: allocation-free per harness rules)
// ---------------------------------------------------------------------------
__device__ float g_gi0[Tc * Bc * 3 * Hc];
__device__ float g_outs[Bc * Tc * Hc];
__device__ float g_h[Bc * Hc];
__device__ float g_h1[Bc * Hc];
__device__ unsigned g_barcnt;
__device__ unsigned g_bargen;
__device__ __half g_abf[(size_t)Bc * Tc * GKB];   // [8192][512] fp16(A)
__device__ __half g_bbf[(size_t)Vc * GKB];        // [32000][512] fp16(B)

// ---------------------------------------------------------------------------
// Baseline-ISA PTX helpers (sm_80+ only; NO 'a'-suffix instructions)
// ---------------------------------------------------------------------------
__device__ __forceinline__ uint32_t smem_u32(const void* p) {
    uint32_t a;
    asm("{ .reg .u64 t; cvta.to.shared.u64 t, %1; cvt.u32.u64 %0, t; }"
        : "=r"(a) : "l"(p));
    return a;
}

#define CP16(dst, src) \
    asm volatile("cp.async.cg.shared.global [%0], [%1], 16;" \
                 :: "r"(dst), "l"(src))
#define CP_COMMIT() asm volatile("cp.async.commit_group;" ::: "memory")
#define CP_WAIT(n)  asm volatile("cp.async.wait_group %0;" :: "n"(n) : "memory")

#define LDSM4(r0, r1, r2, r3, addr) \
    asm volatile("ldmatrix.sync.aligned.m8n8.x4.shared.b16 {%0,%1,%2,%3}, [%4];" \
                 : "=r"(r0), "=r"(r1), "=r"(r2), "=r"(r3) : "r"(addr))

#define MMA16816(d, a, b) \
    asm volatile("mma.sync.aligned.m16n8k16.row.col.f32.f16.f16.f32 " \
                 "{%0,%1,%2,%3}, {%4,%5,%6,%7}, {%8,%9}, {%0,%1,%2,%3};" \
                 : "+f"((d)[0]), "+f"((d)[1]), "+f"((d)[2]), "+f"((d)[3]) \
                 : "r"((a)[0]), "r"((a)[1]), "r"((a)[2]), "r"((a)[3]), \
                   "r"((b)[0]), "r"((b)[1]))

// ---------------------------------------------------------------------------
// Grid barrier for the recurrence kernel
// ---------------------------------------------------------------------------
__device__ __forceinline__ void gridbar() {
    __syncthreads();
    if (threadIdx.x == 0) {
        __threadfence();
        unsigned gen = *(volatile unsigned*)&g_bargen;
        if (atomicAdd(&g_barcnt, 1u) == NBLK - 1) {
            atomicExch(&g_barcnt, 0u);
            __threadfence();
            atomicAdd(&g_bargen, 1u);
        } else {
            while (*(volatile unsigned*)&g_bargen == gen) __nanosleep(64);
        }
        __threadfence();
    }
    __syncthreads();
}

__device__ __forceinline__ float sigm(float v) { return 1.f / (1.f + __expf(-v)); }

// ---------------------------------------------------------------------------
// K1: fp32 GEMM with fused embedding gather (unchanged)
// ---------------------------------------------------------------------------
template <int MODE>
__global__ void __launch_bounds__(256, 2)
gemm_tn(const float* __restrict__ A, const float* __restrict__ W,
        const float* __restrict__ bias, float* __restrict__ C,
        const int* __restrict__ xidx, int N)
{
    __shared__ float As[16 * 128];
    __shared__ float Bs[16 * 128];

    const int tid  = threadIdx.x;
    const int m0   = blockIdx.y * 128;
    const int n0   = blockIdx.x * 128;
    const int lrow = tid >> 2;
    const int lk   = (tid & 3) * 4;
    const int ty   = tid >> 4;
    const int tx   = tid & 15;

    const float *ap0, *ap1;
    {
        int ma0 = m0 + lrow, ma1 = ma0 + 64;
        if (MODE == 1) {
            int r0 = xidx[(ma0 & 31) * Tc + (ma0 >> 5)];
            int r1 = xidx[(ma1 & 31) * Tc + (ma1 >> 5)];
            ap0 = A + (size_t)r0 * Hc;
            ap1 = A + (size_t)r1 * Hc;
        } else {
            ap0 = A + (size_t)ma0 * Hc;
            ap1 = A + (size_t)ma1 * Hc;
        }
    }
    const float* bp0 = W + (size_t)(n0 + lrow) * Hc;
    const float* bp1 = bp0 + (size_t)64 * Hc;

    float acc[8][8];
#pragma unroll
    for (int i = 0; i < 8; i++)
#pragma unroll
        for (int j = 0; j < 8; j++) acc[i][j] = 0.f;

    for (int kt = 0; kt < Hc; kt += 16) {
        float4 a0 = *(const float4*)(ap0 + kt + lk);
        float4 a1 = *(const float4*)(ap1 + kt + lk);
        float4 b0 = *(const float4*)(bp0 + kt + lk);
        float4 b1 = *(const float4*)(bp1 + kt + lk);
        __syncthreads();
        As[(lk + 0) * 128 + lrow]      = a0.x;
        As[(lk + 1) * 128 + lrow]      = a0.y;
        As[(lk + 2) * 128 + lrow]      = a0.z;
        As[(lk + 3) * 128 + lrow]      = a0.w;
        As[(lk + 0) * 128 + lrow + 64] = a1.x;
        As[(lk + 1) * 128 + lrow + 64] = a1.y;
        As[(lk + 2) * 128 + lrow + 64] = a1.z;
        As[(lk + 3) * 128 + lrow + 64] = a1.w;
        Bs[(lk + 0) * 128 + lrow]      = b0.x;
        Bs[(lk + 1) * 128 + lrow]      = b0.y;
        Bs[(lk + 2) * 128 + lrow]      = b0.z;
        Bs[(lk + 3) * 128 + lrow]      = b0.w;
        Bs[(lk + 0) * 128 + lrow + 64] = b1.x;
        Bs[(lk + 1) * 128 + lrow + 64] = b1.y;
        Bs[(lk + 2) * 128 + lrow + 64] = b1.z;
        Bs[(lk + 3) * 128 + lrow + 64] = b1.w;
        __syncthreads();
#pragma unroll
        for (int kk = 0; kk < 16; kk++) {
            float4 av0 = *(const float4*)&As[kk * 128 + ty * 8];
            float4 av1 = *(const float4*)&As[kk * 128 + ty * 8 + 4];
            float4 bv0 = *(const float4*)&Bs[kk * 128 + tx * 8];
            float4 bv1 = *(const float4*)&Bs[kk * 128 + tx * 8 + 4];
            float a[8] = {av0.x, av0.y, av0.z, av0.w, av1.x, av1.y, av1.z, av1.w};
            float b[8] = {bv0.x, bv0.y, bv0.z, bv0.w, bv1.x, bv1.y, bv1.z, bv1.w};
#pragma unroll
            for (int i = 0; i < 8; i++)
#pragma unroll
                for (int j = 0; j < 8; j++) acc[i][j] += a[i] * b[j];
        }
    }

    float bs[8];
#pragma unroll
    for (int j = 0; j < 8; j++) bs[j] = bias[n0 + tx * 8 + j];
#pragma unroll
    for (int i = 0; i < 8; i++) {
        size_t base = (size_t)(m0 + ty * 8 + i) * (size_t)N + n0 + tx * 8;
        float4 o0 = make_float4(acc[i][0] + bs[0], acc[i][1] + bs[1],
                                acc[i][2] + bs[2], acc[i][3] + bs[3]);
        float4 o1 = make_float4(acc[i][4] + bs[4], acc[i][5] + bs[5],
                                acc[i][6] + bs[6], acc[i][7] + bs[7]);
        *(float4*)&C[base]     = o0;
        *(float4*)&C[base + 4] = o1;
    }
}

// ---------------------------------------------------------------------------
// K2: persistent GRU recurrence — 512 threads (16 warps, 4-way k-split).
// Block bk owns j in [4bk, 4bk+4). Thread = (b 0..31, jj 0..3, kh 0..3),
// each handling 128 k. kh>0 write partials; kh==0 reduces + applies cell.
// Weight rows resident in SMEM for whole kernel; lanes broadcast-read them.
// ---------------------------------------------------------------------------
#define REC_SMEM_FLOATS (36 * 512 + 512 * 33 + 2304)   // 150528 B

__global__ void __launch_bounds__(512, 1)
gru_rec(const float* __restrict__ Wih, const float* __restrict__ Whh,
        const float* __restrict__ bih, const float* __restrict__ bhh)
{
    extern __shared__ float sm[];
    float* ws1  = sm;                   // [12][512]  Whh0 rows
    float* ws2  = sm + 12 * 512;        // [24][512]  Wih1|Whh1 rows
    float* hs   = sm + 36 * 512;        // [512][33]  h transposed (padded)
    float* psum = hs + 512 * 33;        // [128][18]  k-partials

    const int tid = threadIdx.x;
    const int bk  = blockIdx.x;
    const int j0  = bk * 4;

    const float* Whh0 = Whh;
    const float* Wih1 = Wih + 1536 * 512;
    const float* Whh1 = Whh + 1536 * 512;

    for (int idx = tid; idx < 12 * 512; idx += 512) {
        int rl = idx >> 9, k = idx & 511;
        int jj = rl / 3, g = rl % 3;
        ws1[idx] = Whh0[(size_t)(g * Hc + j0 + jj) * Hc + k];
    }
    for (int idx = tid; idx < 24 * 512; idx += 512) {
        int rl = idx >> 9, k = idx & 511;
        int jj = rl / 6, g = rl % 6;
        const float* src = (g < 3) ? Wih1 : Whh1;
        int gg = (g < 3) ? g : g - 3;
        ws2[idx] = src[(size_t)(gg * Hc + j0 + jj) * Hc + k];
    }
    {
        int gt = bk * 512 + tid;
        if (gt < Bc * Hc) g_h[gt] = 0.f;
    }

    const int out = tid & 127;
    const int b   = out & 31;
    const int jj  = out >> 5;
    const int kh  = tid >> 7;           // 0..3, 128 k each
    const int j   = j0 + jj;

    const float bhh0r = bhh[j],          bhh0z = bhh[Hc + j],          bhh0n = bhh[2 * Hc + j];
    const float bih1r = bih[3 * Hc + j], bih1z = bih[4 * Hc + j],      bih1n = bih[5 * Hc + j];
    const float bhh1r = bhh[3 * Hc + j], bhh1z = bhh[4 * Hc + j],      bhh1n = bhh[5 * Hc + j];

    gridbar();   // weights + h=0 visible everywhere

    for (int t = 0; t < Tc; t++) {
        // ----- phase 1: layer 0 -----
        // fill hs (transposed) with float4 global loads: 4096 vec / 512 thr
        for (int i4 = tid; i4 < (Bc * Hc) / 4; i4 += 512) {
            int i = i4 * 4;
            int bb = i >> 9, k = i & 511;
            float4 v = __ldcg((const float4*)&g_h[i]);
            hs[(k + 0) * 33 + bb] = v.x;
            hs[(k + 1) * 33 + bb] = v.y;
            hs[(k + 2) * 33 + bb] = v.z;
            hs[(k + 3) * 33 + bb] = v.w;
        }
        __syncthreads();
        {
            const float* wr = ws1 + (jj * 3) * Hc + kh * 128;
            const float* wz = wr + Hc;
            const float* wn = wz + Hc;
            const float* hp = hs + (kh * 128) * 33 + b;
            float sr = 0.f, sz = 0.f, sn = 0.f;
#pragma unroll 8
            for (int k = 0; k < 128; k += 4) {
                float4 vr = *(const float4*)(wr + k);
                float4 vz = *(const float4*)(wz + k);
                float4 vn = *(const float4*)(wn + k);
                float h0 = hp[(k + 0) * 33], h1v = hp[(k + 1) * 33];
                float h2 = hp[(k + 2) * 33], h3v = hp[(k + 3) * 33];
                sr += vr.x * h0 + vr.y * h1v + vr.z * h2 + vr.w * h3v;
                sz += vz.x * h0 + vz.y * h1v + vz.z * h2 + vz.w * h3v;
                sn += vn.x * h0 + vn.y * h1v + vn.z * h2 + vn.w * h3v;
            }
            if (kh) {
                float* ps = psum + out * 18 + (kh - 1) * 3;
                ps[0] = sr; ps[1] = sz; ps[2] = sn;
            }
            __syncthreads();
            if (!kh) {
                const float* ps = psum + out * 18;
#pragma unroll
                for (int p = 0; p < 3; p++) {
                    sr += ps[p * 3 + 0]; sz += ps[p * 3 + 1]; sn += ps[p * 3 + 2];
                }
                const float* gi = g_gi0 + (size_t)(t * Bc + b) * 1536;
                float r = sigm(gi[j] + sr + bhh0r);
                float z = sigm(gi[Hc + j] + sz + bhh0z);
                float n = tanhf(gi[2 * Hc + j] + r * (sn + bhh0n));
                float hprev = hs[j * 33 + b];
                g_h1[b * Hc + j] = (1.f - z) * n + z * hprev;
            }
        }
        gridbar();

        // ----- phase 2: layer 1 (input == hidden == h1) -----
        for (int i4 = tid; i4 < (Bc * Hc) / 4; i4 += 512) {
            int i = i4 * 4;
            int bb = i >> 9, k = i & 511;
            float4 v = __ldcg((const float4*)&g_h1[i]);
            hs[(k + 0) * 33 + bb] = v.x;
            hs[(k + 1) * 33 + bb] = v.y;
            hs[(k + 2) * 33 + bb] = v.z;
            hs[(k + 3) * 33 + bb] = v.w;
        }
        __syncthreads();
        {
            const float* w0 = ws2 + (jj * 6) * Hc + kh * 128;
            const float* hp = hs + (kh * 128) * 33 + b;
            float s0 = 0.f, s1 = 0.f, s2 = 0.f, s3 = 0.f, s4 = 0.f, s5 = 0.f;
#pragma unroll 4
            for (int k = 0; k < 128; k += 4) {
                float4 v0 = *(const float4*)(w0 + k);
                float4 v1 = *(const float4*)(w0 + Hc + k);
                float4 v2 = *(const float4*)(w0 + 2 * Hc + k);
                float4 v3 = *(const float4*)(w0 + 3 * Hc + k);
                float4 v4 = *(const float4*)(w0 + 4 * Hc + k);
                float4 v5 = *(const float4*)(w0 + 5 * Hc + k);
                float h0 = hp[(k + 0) * 33], h1v = hp[(k + 1) * 33];
                float h2 = hp[(k + 2) * 33], h3v = hp[(k + 3) * 33];
                s0 += v0.x * h0 + v0.y * h1v + v0.z * h2 + v0.w * h3v;
                s1 += v1.x * h0 + v1.y * h1v + v1.z * h2 + v1.w * h3v;
                s2 += v2.x * h0 + v2.y * h1v + v2.z * h2 + v2.w * h3v;
                s3 += v3.x * h0 + v3.y * h1v + v3.z * h2 + v3.w * h3v;
                s4 += v4.x * h0 + v4.y * h1v + v4.z * h2 + v4.w * h3v;
                s5 += v5.x * h0 + v5.y * h1v + v5.z * h2 + v5.w * h3v;
            }
            if (kh) {
                float* ps = psum + out * 18 + (kh - 1) * 6;
                ps[0] = s0; ps[1] = s1; ps[2] = s2;
                ps[3] = s3; ps[4] = s4; ps[5] = s5;
            }
            __syncthreads();
            if (!kh) {
                const float* ps = psum + out * 18;
#pragma unroll
                for (int p = 0; p < 3; p++) {
                    s0 += ps[p * 6 + 0]; s1 += ps[p * 6 + 1]; s2 += ps[p * 6 + 2];
                    s3 += ps[p * 6 + 3]; s4 += ps[p * 6 + 4]; s5 += ps[p * 6 + 5];
                }
                float r = sigm((s0 + bih1r) + (s3 + bhh1r));
                float z = sigm((s1 + bih1z) + (s4 + bhh1z));
                float n = tanhf((s2 + bih1n) + r * (s5 + bhh1n));
                float h1v = hs[j * 33 + b];
                float h2 = (1.f - z) * n + z * h1v;
                g_h[b * Hc + j] = h2;
                g_outs[(size_t)(b * Tc + t) * Hc + j] = h2;
            }
        }
        gridbar();
    }
}

// ---------------------------------------------------------------------------
// fp16 conversion kernels (plain rounding, K=512)
// ---------------------------------------------------------------------------
__global__ void conv_a() {
    int i = blockIdx.x * 256 + threadIdx.x;
    if (i >= Bc * Tc * Hc) return;
    g_abf[i] = __float2half_rn(g_outs[i]);
}

__global__ void conv_b(const float* __restrict__ Wout) {
    int i = blockIdx.x * 256 + threadIdx.x;
    if (i >= Vc * Hc) return;
    g_bbf[i] = __float2half_rn(Wout[i]);
}

// ---------------------------------------------------------------------------
// K3: HMMA fp16 GEMM (unchanged from R15 — 6406us config)
// ---------------------------------------------------------------------------
__global__ void __launch_bounds__(256, 2)
gemm_hmma(const float* __restrict__ bout, float* __restrict__ C)
{
    extern __shared__ __align__(16) char smc[];
    const uint32_t sb = smem_u32(smc);
    const int tid  = threadIdx.x;
    const int lane = tid & 31;
    const int wid  = tid >> 5;
    const int wm   = wid & 3;
    const int wn   = wid >> 2;
    const int m0   = blockIdx.x * 128;
    const int n0   = blockIdx.y * 128;

    const __half* Ag = g_abf + (size_t)m0 * GKB;
    const __half* Bg = g_bbf + (size_t)n0 * GKB;

    float acc[2][8][4];
#pragma unroll
    for (int mb = 0; mb < 2; mb++)
#pragma unroll
        for (int nb = 0; nb < 8; nb++)
#pragma unroll
            for (int q = 0; q < 4; q++) acc[mb][nb][q] = 0.f;

    auto load_chunk = [&](int c) {
        const uint32_t stg = sb + (uint32_t)(c & 3) * STG_BYTES;
        const int kc = c * KCH;
#pragma unroll
        for (int r = 0; r < 2; r++) {
            int seg = tid + r * 256;
            int row = seg >> 2, i = seg & 3;
            CP16(stg + (uint32_t)(row * SROW + i * 16),
                 Ag + (size_t)row * GKB + kc + i * 8);
        }
        const uint32_t stgB = stg + 128 * SROW;
#pragma unroll
        for (int r = 0; r < 2; r++) {
            int seg = tid + r * 256;
            int row = seg >> 2, i = seg & 3;
            CP16(stgB + (uint32_t)(row * SROW + i * 16),
                 Bg + (size_t)row * GKB + kc + i * 8);
        }
    };

    load_chunk(0); CP_COMMIT();
    load_chunk(1); CP_COMMIT();
    load_chunk(2); CP_COMMIT();

    for (int c = 0; c < NCHUNK; c++) {
        CP_WAIT(2);
        __syncthreads();

        if (c + 3 < NCHUNK) load_chunk(c + 3);
        CP_COMMIT();

        const uint32_t aB = sb + (uint32_t)(c & 3) * STG_BYTES;
        const uint32_t bB = aB + 128 * SROW;

#pragma unroll
        for (int kk = 0; kk < 2; kk++) {
            uint32_t a[2][4];
            {
                uint32_t addr = aB + (uint32_t)((wm * 32 + (lane & 15)) * SROW
                                  + (kk * 16 + ((lane >> 4) << 3)) * 2);
                LDSM4(a[0][0], a[0][1], a[0][2], a[0][3], addr);
                LDSM4(a[1][0], a[1][1], a[1][2], a[1][3], addr + 16 * SROW);
            }
            uint32_t b[8][2];
            {
                const int q = lane >> 3, rr = lane & 7;
                const int nbase = wn * 64 + ((q & 2) << 2) + rr;
                const int kcol  = kk * 16 + ((q & 1) << 3);
#pragma unroll
                for (int p = 0; p < 4; p++) {
                    uint32_t addr = bB + (uint32_t)((nbase + p * 16) * SROW + kcol * 2);
                    LDSM4(b[2 * p][0], b[2 * p][1], b[2 * p + 1][0], b[2 * p + 1][1], addr);
                }
            }
#pragma unroll
            for (int mb = 0; mb < 2; mb++)
#pragma unroll
                for (int nb = 0; nb < 8; nb++)
                    MMA16816(acc[mb][nb], a[mb], b[nb]);
        }
    }

#pragma unroll
    for (int mb = 0; mb < 2; mb++) {
        const int row = m0 + wm * 32 + mb * 16 + (lane >> 2);
#pragma unroll
        for (int nb = 0; nb < 8; nb++) {
            const int col = n0 + wn * 64 + nb * 8 + (lane & 3) * 2;
            const float b0 = __ldg(&bout[col]);
            const float b1 = __ldg(&bout[col + 1]);
            float2 o0 = make_float2(acc[mb][nb][0] + b0, acc[mb][nb][1] + b1);
            float2 o1 = make_float2(acc[mb][nb][2] + b0, acc[mb][nb][3] + b1);
            *(float2*)&C[(size_t)row * Vc + col]       = o0;
            *(float2*)&C[(size_t)(row + 8) * Vc + col] = o1;
        }
    }
}

// ---------------------------------------------------------------------------
// Launch
// ---------------------------------------------------------------------------
extern "C" void kernel_launch(void* const* d_in, const int* in_sizes, int n_in,
                              void* d_out, int out_size)
{
    const int*   x    = (const int*)d_in[0];
    const float* emb  = (const float*)d_in[1];
    const float* Wih  = (const float*)d_in[2];
    const float* Whh  = (const float*)d_in[3];
    const float* bih  = (const float*)d_in[4];
    const float* bhh  = (const float*)d_in[5];
    const float* Wout = (const float*)d_in[6];
    const float* bout = (const float*)d_in[7];
    float* out = (float*)d_out;

    void* p;
    cudaGetSymbolAddress(&p, g_gi0);  float* gi0 = (float*)p;

    // K1: gi0[t*32+b][0:1536] = emb[x[b][t]] @ Wih0^T + bih0
    dim3 g1(1536 / 128, (Bc * Tc) / 128);
    gemm_tn<1><<<g1, 256>>>(emb, Wih, bih, gi0, x, 1536);

    // B fp16 conversion (independent of recurrence)
    conv_b<<<(Vc * Hc + 255) / 256, 256>>>(Wout);

    // K2: persistent recurrence (512 threads, 4-way k-split)
    size_t smem = REC_SMEM_FLOATS * sizeof(float);   // 150528 B
    cudaFuncSetAttribute(gru_rec, cudaFuncAttributeMaxDynamicSharedMemorySize, (int)smem);
    gru_rec<<<NBLK, 512, smem>>>(Wih, Whh, bih, bhh);

    // A fp16 conversion (needs g_outs)
    conv_a<<<(Bc * Tc * Hc + 255) / 256, 256>>>();

    // K3: logits = A @ B^T + bout via mma.sync fp16 (K=512)
    cudaFuncSetAttribute(gemm_hmma, cudaFuncAttributeMaxDynamicSharedMemorySize, TC_SMEM);
    dim3 g3((Bc * Tc) / 128, Vc / 128);   // (64, 250), m fastest
    gemm_hmma<<<g3, 256, TC_SMEM>>>(bout, out);
}